// round 1
// baseline (speedup 1.0000x reference)
#include <cuda_runtime.h>

// Problem constants
#define S 2048
#define H 1024
#define E 8
#define INTER 2048
#define TWO_I 4096
#define ALPHA 1.702f
#define LIMIT 7.0f

// Routing scratch (device globals — no allocation allowed)
__device__ int   g_cnt[E];
__device__ int   g_tok[E * S];     // token index per (expert, position)
__device__ float g_wt[E * S];      // combine weight per (expert, position)
// Activation scratch: [E][S][INTER] fp32 = 128 MB
__device__ float g_act[(size_t)E * S * INTER];

// ---------------------------------------------------------------------------
// init: zero per-expert counters
// ---------------------------------------------------------------------------
__global__ void init_kernel() {
    if (threadIdx.x < E) g_cnt[threadIdx.x] = 0;
}

// ---------------------------------------------------------------------------
// Router: logits = x @ router_w + b ; top-2 ; softmax over the 2 ; bucket
// One block (256 threads) per token.
// ---------------------------------------------------------------------------
__global__ __launch_bounds__(256) void router_kernel(
    const float* __restrict__ x,
    const float* __restrict__ rw,   // [H, E]
    const float* __restrict__ rb)   // [E]
{
    int t = blockIdx.x;
    int tid = threadIdx.x;
    const float* xr = x + (size_t)t * H;

    float acc[E];
#pragma unroll
    for (int e = 0; e < E; e++) acc[e] = 0.0f;

    for (int h = tid; h < H; h += 256) {
        float xv = xr[h];
        const float4* wrow = (const float4*)(rw + (size_t)h * E);
        float4 w0 = wrow[0];
        float4 w1 = wrow[1];
        acc[0] += xv * w0.x; acc[1] += xv * w0.y;
        acc[2] += xv * w0.z; acc[3] += xv * w0.w;
        acc[4] += xv * w1.x; acc[5] += xv * w1.y;
        acc[6] += xv * w1.z; acc[7] += xv * w1.w;
    }

    __shared__ float sm[256 * E];
#pragma unroll
    for (int e = 0; e < E; e++) sm[tid * E + e] = acc[e];
    __syncthreads();
    for (int s = 128; s > 0; s >>= 1) {
        if (tid < s) {
#pragma unroll
            for (int e = 0; e < E; e++)
                sm[tid * E + e] += sm[(tid + s) * E + e];
        }
        __syncthreads();
    }

    if (tid == 0) {
        float v[E];
#pragma unroll
        for (int e = 0; e < E; e++) v[e] = sm[e] + rb[e];
        // top-1 (earliest index on ties, matching jax top_k)
        int i0 = 0;
#pragma unroll
        for (int e = 1; e < E; e++) if (v[e] > v[i0]) i0 = e;
        // top-2
        int i1 = -1;
#pragma unroll
        for (int e = 0; e < E; e++) {
            if (e == i0) continue;
            if (i1 < 0 || v[e] > v[i1]) i1 = e;
        }
        // softmax over the two selected logits (v[i0] >= v[i1])
        float e1 = expf(v[i1] - v[i0]);
        float denom = 1.0f + e1;
        float w0 = 1.0f / denom;
        float w1 = e1 / denom;

        int p0 = atomicAdd(&g_cnt[i0], 1);
        g_tok[i0 * S + p0] = t;
        g_wt[i0 * S + p0] = w0;
        int p1 = atomicAdd(&g_cnt[i1], 1);
        g_tok[i1 * S + p1] = t;
        g_wt[i1 * S + p1] = w1;
    }
}

// ---------------------------------------------------------------------------
// gate_up GEMM + activation -> g_act
// Block tile 64 tokens x 64 act-columns; computes BOTH the gate column block
// [n0, n0+64) and the up column block [n0+INTER, n0+INTER+64) in one K loop.
// 256 threads, 4x4 register tile each (x2 for gate/up).
// ---------------------------------------------------------------------------
__global__ __launch_bounds__(256) void gate_up_kernel(
    const float* __restrict__ x,    // [S, H]
    const float* __restrict__ gup,  // [E, H, 2I]
    const float* __restrict__ gub)  // [E, 2I]
{
    int e = blockIdx.z;
    int cnt = g_cnt[e];
    int mt = blockIdx.x;
    int nt = blockIdx.y;
    if (mt * 64 >= cnt) return;

    __shared__ float As[64][17];
    __shared__ float Bg[16][64];
    __shared__ float Bu[16][64];

    int tid = threadIdx.x;
    int tx = tid & 15;
    int ty = tid >> 4;

    // A-load mapping: 4 threads per row, one float4 each
    int lr = tid >> 2;
    int lk = (tid & 3) * 4;
    int grow = mt * 64 + lr;
    int tokl = g_tok[e * S + min(grow, cnt - 1)];
    tokl = min(max(tokl, 0), S - 1);
    const float* xrow = x + (size_t)tokl * H;

    // B-load mapping: 16 threads per k-row, one float4 each
    int bkr = tid >> 4;
    int bco = (tid & 15) * 4;
    const float* gbase = gup + (size_t)e * H * TWO_I;
    int n0 = nt * 64;

    float accg[4][4], accu[4][4];
#pragma unroll
    for (int i = 0; i < 4; i++)
#pragma unroll
        for (int j = 0; j < 4; j++) { accg[i][j] = 0.0f; accu[i][j] = 0.0f; }

    for (int k0 = 0; k0 < H; k0 += 16) {
        float4 av = *(const float4*)(xrow + k0 + lk);
        As[lr][lk + 0] = av.x; As[lr][lk + 1] = av.y;
        As[lr][lk + 2] = av.z; As[lr][lk + 3] = av.w;

        const float* brow = gbase + (size_t)(k0 + bkr) * TWO_I;
        float4 bg = *(const float4*)(brow + n0 + bco);
        float4 bu = *(const float4*)(brow + INTER + n0 + bco);
        *(float4*)&Bg[bkr][bco] = bg;
        *(float4*)&Bu[bkr][bco] = bu;
        __syncthreads();

#pragma unroll
        for (int kk = 0; kk < 16; kk++) {
            float ra[4];
#pragma unroll
            for (int i = 0; i < 4; i++) ra[i] = As[ty * 4 + i][kk];
            float4 rbg = *(float4*)&Bg[kk][tx * 4];
            float4 rbu = *(float4*)&Bu[kk][tx * 4];
            float rg[4] = {rbg.x, rbg.y, rbg.z, rbg.w};
            float ru[4] = {rbu.x, rbu.y, rbu.z, rbu.w};
#pragma unroll
            for (int i = 0; i < 4; i++) {
#pragma unroll
                for (int j = 0; j < 4; j++) {
                    accg[i][j] += ra[i] * rg[j];
                    accu[i][j] += ra[i] * ru[j];
                }
            }
        }
        __syncthreads();
    }

    const float* gbias = gub + (size_t)e * TWO_I;
#pragma unroll
    for (int i = 0; i < 4; i++) {
        int row = mt * 64 + ty * 4 + i;
        if (row >= cnt) continue;
        float tmp[4];
#pragma unroll
        for (int j = 0; j < 4; j++) {
            int n = n0 + tx * 4 + j;
            float g = accg[i][j] + gbias[n];
            float u = accu[i][j] + gbias[INTER + n];
            g = fminf(g, LIMIT);
            u = fminf(fmaxf(u, -LIMIT), LIMIT);
            float glu = g / (1.0f + expf(-ALPHA * g));
            tmp[j] = (u + 1.0f) * glu;
        }
        float4 o = make_float4(tmp[0], tmp[1], tmp[2], tmp[3]);
        *(float4*)(g_act + ((size_t)(e * S + row)) * INTER + n0 + tx * 4) = o;
    }
}

// ---------------------------------------------------------------------------
// down GEMM + bias + weighted combine (atomicAdd; exactly 2 adds per output
// element -> commutative -> deterministic)
// ---------------------------------------------------------------------------
__global__ __launch_bounds__(256) void down_kernel(
    const float* __restrict__ dwn,   // [E, INTER, H]
    const float* __restrict__ dbias, // [E, H]
    float* __restrict__ out)         // [S, H]
{
    int e = blockIdx.z;
    int cnt = g_cnt[e];
    int mt = blockIdx.x;
    int ht = blockIdx.y;
    if (mt * 64 >= cnt) return;

    __shared__ float As[64][17];
    __shared__ float Bs[16][64];

    int tid = threadIdx.x;
    int tx = tid & 15;
    int ty = tid >> 4;

    int lr = tid >> 2;
    int lk = (tid & 3) * 4;
    int grow = mt * 64 + lr;
    const float* arow = g_act + (size_t)(e * S + min(grow, cnt - 1)) * INTER;

    int bkr = tid >> 4;
    int bco = (tid & 15) * 4;
    const float* dbase = dwn + (size_t)e * INTER * H;
    int h0 = ht * 64;

    float acc[4][4];
#pragma unroll
    for (int i = 0; i < 4; i++)
#pragma unroll
        for (int j = 0; j < 4; j++) acc[i][j] = 0.0f;

    for (int k0 = 0; k0 < INTER; k0 += 16) {
        float4 av = *(const float4*)(arow + k0 + lk);
        As[lr][lk + 0] = av.x; As[lr][lk + 1] = av.y;
        As[lr][lk + 2] = av.z; As[lr][lk + 3] = av.w;

        float4 bv = *(const float4*)(dbase + (size_t)(k0 + bkr) * H + h0 + bco);
        *(float4*)&Bs[bkr][bco] = bv;
        __syncthreads();

#pragma unroll
        for (int kk = 0; kk < 16; kk++) {
            float ra[4];
#pragma unroll
            for (int i = 0; i < 4; i++) ra[i] = As[ty * 4 + i][kk];
            float4 rb = *(float4*)&Bs[kk][tx * 4];
            float rbv[4] = {rb.x, rb.y, rb.z, rb.w};
#pragma unroll
            for (int i = 0; i < 4; i++) {
#pragma unroll
                for (int j = 0; j < 4; j++)
                    acc[i][j] += ra[i] * rbv[j];
            }
        }
        __syncthreads();
    }

    const float* bias = dbias + (size_t)e * H;
#pragma unroll
    for (int i = 0; i < 4; i++) {
        int row = mt * 64 + ty * 4 + i;
        if (row >= cnt) continue;
        int tok = g_tok[e * S + row];
        float w = g_wt[e * S + row];
        float* orow = out + (size_t)tok * H;
#pragma unroll
        for (int j = 0; j < 4; j++) {
            int h = h0 + tx * 4 + j;
            float r = acc[i][j] + bias[h];
            atomicAdd(&orow[h], w * r);
        }
    }
}

// ---------------------------------------------------------------------------
extern "C" void kernel_launch(void* const* d_in, const int* in_sizes, int n_in,
                              void* d_out, int out_size) {
    const float* x     = (const float*)d_in[0];
    const float* rw    = (const float*)d_in[1];
    const float* rb    = (const float*)d_in[2];
    const float* gup   = (const float*)d_in[3];
    const float* gub   = (const float*)d_in[4];
    const float* dwn   = (const float*)d_in[5];
    const float* dbias = (const float*)d_in[6];
    float* out = (float*)d_out;

    cudaMemsetAsync(out, 0, (size_t)out_size * sizeof(float));
    init_kernel<<<1, 32>>>();
    router_kernel<<<S, 256>>>(x, rw, rb);

    dim3 gb(S / 64, INTER / 64, E);   // (32, 32, 8) — blocks early-exit past bucket count
    gate_up_kernel<<<gb, 256>>>(x, gup, gub);

    dim3 gc(S / 64, H / 64, E);       // (32, 16, 8)
    down_kernel<<<gc, 256>>>(dwn, dbias, out);
}

// round 6
// speedup vs baseline: 2.2698x; 2.2698x over previous
#include <cuda_runtime.h>
#include <cuda_bf16.h>
#include <cstdint>

#define S 2048
#define H 1024
#define E 8
#define INTER 2048
#define TWO_I 4096
#define ALPHA 1.702f
#define LIMIT 7.0f

// ---------------- device scratch (no allocation allowed) ----------------
// NOTE: these are ONLY referenced from device code (never passed as kernel
// args from host -- that passes the host shadow address and on GB300/ATS
// silently writes host memory).
__device__ int   g_cnt[E];
__device__ int   g_tok[E * S];
__device__ float g_wt[E * S];
__device__ __align__(128) __nv_bfloat16 g_xhi[S * H];
__device__ __align__(128) __nv_bfloat16 g_xlo[S * H];
// gate_up weights transposed+split: [E][N=4096][K=1024]
__device__ __align__(128) __nv_bfloat16 g_guh[(size_t)E * TWO_I * H];
__device__ __align__(128) __nv_bfloat16 g_gul[(size_t)E * TWO_I * H];
// down weights transposed+split: [E][N=H][K=INTER]
__device__ __align__(128) __nv_bfloat16 g_dwh[(size_t)E * H * INTER];
__device__ __align__(128) __nv_bfloat16 g_dwl[(size_t)E * H * INTER];
// activations split: [E][S][INTER]
__device__ __align__(128) __nv_bfloat16 g_ah[(size_t)E * S * INTER];
__device__ __align__(128) __nv_bfloat16 g_al[(size_t)E * S * INTER];

// ---------------- helpers ----------------
__device__ __forceinline__ uint32_t s2u(const void* p) {
    uint32_t a;
    asm("{ .reg .u64 t; cvta.to.shared.u64 t, %1; cvt.u32.u64 %0, t; }" : "=r"(a) : "l"(p));
    return a;
}
__device__ __forceinline__ uint32_t swz128(uint32_t o) { return o ^ ((o >> 3) & 0x70); }

#define CP16(dst, src) \
    asm volatile("cp.async.cg.shared.global [%0], [%1], 16;" :: "r"(dst), "l"(src) : "memory")
#define CP_COMMIT() asm volatile("cp.async.commit_group;" ::: "memory")
#define CP_WAIT0()  asm volatile("cp.async.wait_group 0;" ::: "memory")
#define CP_WAIT1()  asm volatile("cp.async.wait_group 1;" ::: "memory")

__device__ __forceinline__ void ldsm4(uint32_t addr, uint32_t* r) {
    asm volatile("ldmatrix.sync.aligned.m8n8.x4.shared.b16 {%0,%1,%2,%3}, [%4];"
                 : "=r"(r[0]), "=r"(r[1]), "=r"(r[2]), "=r"(r[3]) : "r"(addr));
}
__device__ __forceinline__ void mma16816(float* d, const uint32_t* a, uint32_t b0, uint32_t b1) {
    asm volatile(
        "mma.sync.aligned.m16n8k16.row.col.f32.bf16.bf16.f32 "
        "{%0,%1,%2,%3}, {%4,%5,%6,%7}, {%8,%9}, {%0,%1,%2,%3};"
        : "+f"(d[0]), "+f"(d[1]), "+f"(d[2]), "+f"(d[3])
        : "r"(a[0]), "r"(a[1]), "r"(a[2]), "r"(a[3]), "r"(b0), "r"(b1));
}

// Stage layout: Ah 16K | Al 16K | Bh 16K | Bl 16K = 64KB; 2 stages
#define STAGE 65536
#define SMEM_REQ (1024 + 2 * STAGE)

// one K=64 chunk of 3-term split MMA, block tile 128x128, warp tile 64x32
__device__ __forceinline__ void compute_chunk(
    uint32_t sA, uint32_t sAl, uint32_t sB, uint32_t sBl,
    int wm, int wn, int lane, float acc[4][4][4])
{
    int arow = wm + (lane & 15);
    int brow = wn + (lane & 15);
    uint32_t klane = (uint32_t)((lane >> 4) << 4);
#pragma unroll
    for (int ks = 0; ks < 4; ks++) {
        uint32_t ko = (uint32_t)(ks * 32) + klane;
        uint32_t ah[4][4], al[4][4];
#pragma unroll
        for (int mf = 0; mf < 4; mf++) {
            uint32_t off = swz128((uint32_t)((arow + mf * 16) * 128) + ko);
            ldsm4(sA + off, ah[mf]);
            ldsm4(sAl + off, al[mf]);
        }
#pragma unroll
        for (int nh = 0; nh < 2; nh++) {
            uint32_t boff = swz128((uint32_t)((brow + nh * 16) * 128) + ko);
            uint32_t bh[4], bl[4];
            ldsm4(sB + boff, bh);
            ldsm4(sBl + boff, bl);
#pragma unroll
            for (int mf = 0; mf < 4; mf++) {
                mma16816(acc[mf][2 * nh],     ah[mf], bh[0], bh[2]);
                mma16816(acc[mf][2 * nh],     al[mf], bh[0], bh[2]);
                mma16816(acc[mf][2 * nh],     ah[mf], bl[0], bl[2]);
                mma16816(acc[mf][2 * nh + 1], ah[mf], bh[1], bh[3]);
                mma16816(acc[mf][2 * nh + 1], al[mf], bh[1], bh[3]);
                mma16816(acc[mf][2 * nh + 1], ah[mf], bl[1], bl[3]);
            }
        }
    }
}

__device__ __forceinline__ void issue_chunk(
    uint32_t base, int k0,
    const __nv_bfloat16* Ah, const __nv_bfloat16* Al,
    const __nv_bfloat16* Bh, const __nv_bfloat16* Bl,
    const size_t* asrc, const size_t* bsrc,
    const uint32_t* adst, const uint32_t* bdst)
{
#pragma unroll
    for (int i = 0; i < 4; i++) {
        CP16(base +         adst[i], (const char*)(Ah + asrc[i] + k0));
        CP16(base + 16384 + adst[i], (const char*)(Al + asrc[i] + k0));
        CP16(base + 32768 + bdst[i], (const char*)(Bh + bsrc[i] + k0));
        CP16(base + 49152 + bdst[i], (const char*)(Bl + bsrc[i] + k0));
    }
    CP_COMMIT();
}

// ---------------------------------------------------------------------------
__global__ void init_kernel() {
    if (threadIdx.x < E) g_cnt[threadIdx.x] = 0;
}

// ---------------------------------------------------------------------------
__global__ __launch_bounds__(256) void router_kernel(
    const float* __restrict__ x, const float* __restrict__ rw, const float* __restrict__ rb)
{
    int t = blockIdx.x;
    int tid = threadIdx.x;
    const float* xr = x + (size_t)t * H;

    float acc[E];
#pragma unroll
    for (int e = 0; e < E; e++) acc[e] = 0.0f;
    for (int h = tid; h < H; h += 256) {
        float xv = xr[h];
        const float4* wrow = (const float4*)(rw + (size_t)h * E);
        float4 w0 = wrow[0], w1 = wrow[1];
        acc[0] += xv * w0.x; acc[1] += xv * w0.y; acc[2] += xv * w0.z; acc[3] += xv * w0.w;
        acc[4] += xv * w1.x; acc[5] += xv * w1.y; acc[6] += xv * w1.z; acc[7] += xv * w1.w;
    }
    __shared__ float sm[256 * E];
#pragma unroll
    for (int e = 0; e < E; e++) sm[tid * E + e] = acc[e];
    __syncthreads();
    for (int s = 128; s > 0; s >>= 1) {
        if (tid < s) {
#pragma unroll
            for (int e = 0; e < E; e++) sm[tid * E + e] += sm[(tid + s) * E + e];
        }
        __syncthreads();
    }
    if (tid == 0) {
        float v[E];
#pragma unroll
        for (int e = 0; e < E; e++) v[e] = sm[e] + rb[e];
        int i0 = 0;
#pragma unroll
        for (int e = 1; e < E; e++) if (v[e] > v[i0]) i0 = e;
        int i1 = -1;
#pragma unroll
        for (int e = 0; e < E; e++) {
            if (e == i0) continue;
            if (i1 < 0 || v[e] > v[i1]) i1 = e;
        }
        float e1 = expf(v[i1] - v[i0]);
        float den = 1.0f + e1;
        int p0 = atomicAdd(&g_cnt[i0], 1);
        g_tok[i0 * S + p0] = t; g_wt[i0 * S + p0] = 1.0f / den;
        int p1 = atomicAdd(&g_cnt[i1], 1);
        g_tok[i1 * S + p1] = t; g_wt[i1 * S + p1] = e1 / den;
    }
}

// ---------------------------------------------------------------------------
__global__ __launch_bounds__(256) void conv_x_kernel(const float* __restrict__ x) {
    int i = blockIdx.x * 256 + threadIdx.x;           // 4 elements each
    float4 v = ((const float4*)x)[i];
    __nv_bfloat16 h0 = __float2bfloat16(v.x), h1 = __float2bfloat16(v.y);
    __nv_bfloat16 h2 = __float2bfloat16(v.z), h3 = __float2bfloat16(v.w);
    __nv_bfloat16 l0 = __float2bfloat16(v.x - __bfloat162float(h0));
    __nv_bfloat16 l1 = __float2bfloat16(v.y - __bfloat162float(h1));
    __nv_bfloat16 l2 = __float2bfloat16(v.z - __bfloat162float(h2));
    __nv_bfloat16 l3 = __float2bfloat16(v.w - __bfloat162float(h3));
    ((__nv_bfloat162*)g_xhi)[2 * i]     = __halves2bfloat162(h0, h1);
    ((__nv_bfloat162*)g_xhi)[2 * i + 1] = __halves2bfloat162(h2, h3);
    ((__nv_bfloat162*)g_xlo)[2 * i]     = __halves2bfloat162(l0, l1);
    ((__nv_bfloat162*)g_xlo)[2 * i + 1] = __halves2bfloat162(l2, l3);
}

// ---------------------------------------------------------------------------
// weight transpose + split, outputs bound in DEVICE code (template param).
// in [E][R][C] fp32 -> out [E][C][R] bf16 hi/lo. Tile 64(R) x 32(C).
// ---------------------------------------------------------------------------
template <int WHICH>   // 0 = gate_up (R=H, C=2I), 1 = down (R=INTER, C=H)
__global__ __launch_bounds__(256) void transpose_split_kernel(const float* __restrict__ in)
{
    const int R = (WHICH == 0) ? H : INTER;
    const int C = (WHICH == 0) ? TWO_I : H;
    __nv_bfloat16* ohi = (WHICH == 0) ? g_guh : g_dwh;
    __nv_bfloat16* olo = (WHICH == 0) ? g_gul : g_dwl;

    int e = blockIdx.z;
    int r0 = blockIdx.x * 64;
    int c0 = blockIdx.y * 32;
    __shared__ float t[64][33];
    int tx = threadIdx.x & 31, ty = threadIdx.x >> 5;
    const float* ib = in + ((size_t)e * R + r0) * C + c0;
#pragma unroll
    for (int i = 0; i < 8; i++)
        t[ty + 8 * i][tx] = ib[(size_t)(ty + 8 * i) * C + tx];
    __syncthreads();
#pragma unroll
    for (int i = 0; i < 4; i++) {
        int c = ty + 8 * i;
        float a = t[2 * tx][c], b = t[2 * tx + 1][c];
        __nv_bfloat16 ah = __float2bfloat16(a), bh = __float2bfloat16(b);
        __nv_bfloat16 al = __float2bfloat16(a - __bfloat162float(ah));
        __nv_bfloat16 bl = __float2bfloat16(b - __bfloat162float(bh));
        size_t o = ((size_t)e * C + c0 + c) * R + r0 + 2 * tx;
        *(__nv_bfloat162*)(ohi + o) = __halves2bfloat162(ah, bh);
        *(__nv_bfloat162*)(olo + o) = __halves2bfloat162(al, bl);
    }
}

// ---------------------------------------------------------------------------
// gate_up: CTA = (expert, 128-token M-tile, 64-j N-tile). B tile rows interleave
// gate/up so each thread's (c0,c1) accumulator pair = (gate_j, up_j).
// K = H = 1024, 16 chunks of 64; cp.async double-buffered.
// ---------------------------------------------------------------------------
__global__ __launch_bounds__(256, 1) void gateup_mma_kernel(const float* __restrict__ gub) {
    int e = blockIdx.z, mt = blockIdx.x, nt = blockIdx.y;
    int cnt = g_cnt[e];
    if (mt * 128 >= cnt) return;

    extern __shared__ char smem[];
    uint32_t T0 = (s2u(smem) + 1023) & ~1023u;
    int tid = threadIdx.x, wid = tid >> 5, lane = tid & 31;
    int wm = (wid >> 2) * 64, wn = (wid & 3) * 32;
    int j0 = nt * 64;

    int seg = tid & 7;
    size_t asrc[4], bsrc[4];
    uint32_t adst[4], bdst[4];
#pragma unroll
    for (int i = 0; i < 4; i++) {
        int row = (tid >> 3) + 32 * i;                 // 0..127
        int tr = min(mt * 128 + row, cnt - 1);
        int tok = g_tok[e * S + tr];
        asrc[i] = (size_t)tok * H + seg * 8;
        int br = (row & 1) ? (INTER + j0 + (row >> 1)) : (j0 + (row >> 1));
        bsrc[i] = ((size_t)e * TWO_I + br) * H + seg * 8;
        adst[i] = swz128((uint32_t)(row * 128 + seg * 16));
        bdst[i] = adst[i];
    }

    float acc[4][4][4];
#pragma unroll
    for (int a = 0; a < 4; a++)
#pragma unroll
        for (int b = 0; b < 4; b++)
#pragma unroll
            for (int c = 0; c < 4; c++) acc[a][b][c] = 0.0f;

    issue_chunk(T0, 0, g_xhi, g_xlo, g_guh, g_gul, asrc, bsrc, adst, bdst);
#pragma unroll 1
    for (int c = 0; c < 16; c++) {
        if (c + 1 < 16) {
            issue_chunk(T0 + ((c + 1) & 1) * STAGE, (c + 1) * 64,
                        g_xhi, g_xlo, g_guh, g_gul, asrc, bsrc, adst, bdst);
            CP_WAIT1();
        } else {
            CP_WAIT0();
        }
        __syncthreads();
        uint32_t base = T0 + (c & 1) * STAGE;
        compute_chunk(base, base + 16384, base + 32768, base + 49152, wm, wn, lane, acc);
        __syncthreads();
    }

    const float* gb = gub + (size_t)e * TWO_I;
#pragma unroll
    for (int mf = 0; mf < 4; mf++) {
        int r0 = wm + mf * 16 + (lane >> 2);
#pragma unroll
        for (int half = 0; half < 2; half++) {
            int mrow = mt * 128 + r0 + half * 8;
            if (mrow >= cnt) continue;
            size_t abase = ((size_t)e * S + mrow) * INTER;
#pragma unroll
            for (int nf = 0; nf < 4; nf++) {
                int nn = wn + nf * 8 + 2 * (lane & 3);
                int j = j0 + (nn >> 1);
                float g = acc[mf][nf][half * 2 + 0] + gb[j];
                float u = acc[mf][nf][half * 2 + 1] + gb[INTER + j];
                g = fminf(g, LIMIT);
                u = fminf(fmaxf(u, -LIMIT), LIMIT);
                float glu = g / (1.0f + __expf(-ALPHA * g));
                float av = (u + 1.0f) * glu;
                __nv_bfloat16 hi = __float2bfloat16(av);
                __nv_bfloat16 lo = __float2bfloat16(av - __bfloat162float(hi));
                g_ah[abase + j] = hi;
                g_al[abase + j] = lo;
            }
        }
    }
}

// ---------------------------------------------------------------------------
// down: CTA = (expert, 128-row M-tile, 128-h N-tile). K = INTER = 2048, 32 chunks.
// Epilogue: bias + weighted atomicAdd (2 adds/element -> deterministic).
// ---------------------------------------------------------------------------
__global__ __launch_bounds__(256, 1) void down_mma_kernel(
    const float* __restrict__ dbias, float* __restrict__ out)
{
    int e = blockIdx.z, mt = blockIdx.x, nt = blockIdx.y;
    int cnt = g_cnt[e];
    if (mt * 128 >= cnt) return;

    extern __shared__ char smem[];
    uint32_t T0 = (s2u(smem) + 1023) & ~1023u;
    int tid = threadIdx.x, wid = tid >> 5, lane = tid & 31;
    int wm = (wid >> 2) * 64, wn = (wid & 3) * 32;
    int h0 = nt * 128;

    int seg = tid & 7;
    size_t asrc[4], bsrc[4];
    uint32_t adst[4], bdst[4];
#pragma unroll
    for (int i = 0; i < 4; i++) {
        int row = (tid >> 3) + 32 * i;
        int tr = min(mt * 128 + row, cnt - 1);
        asrc[i] = ((size_t)e * S + tr) * INTER + seg * 8;
        bsrc[i] = ((size_t)e * H + h0 + row) * INTER + seg * 8;
        adst[i] = swz128((uint32_t)(row * 128 + seg * 16));
        bdst[i] = adst[i];
    }

    float acc[4][4][4];
#pragma unroll
    for (int a = 0; a < 4; a++)
#pragma unroll
        for (int b = 0; b < 4; b++)
#pragma unroll
            for (int c = 0; c < 4; c++) acc[a][b][c] = 0.0f;

    issue_chunk(T0, 0, g_ah, g_al, g_dwh, g_dwl, asrc, bsrc, adst, bdst);
#pragma unroll 1
    for (int c = 0; c < 32; c++) {
        if (c + 1 < 32) {
            issue_chunk(T0 + ((c + 1) & 1) * STAGE, (c + 1) * 64,
                        g_ah, g_al, g_dwh, g_dwl, asrc, bsrc, adst, bdst);
            CP_WAIT1();
        } else {
            CP_WAIT0();
        }
        __syncthreads();
        uint32_t base = T0 + (c & 1) * STAGE;
        compute_chunk(base, base + 16384, base + 32768, base + 49152, wm, wn, lane, acc);
        __syncthreads();
    }

    const float* db = dbias + (size_t)e * H;
#pragma unroll
    for (int mf = 0; mf < 4; mf++) {
        int r0 = wm + mf * 16 + (lane >> 2);
#pragma unroll
        for (int half = 0; half < 2; half++) {
            int mrow = mt * 128 + r0 + half * 8;
            if (mrow >= cnt) continue;
            int tok = g_tok[e * S + mrow];
            float w = g_wt[e * S + mrow];
            float* orow = out + (size_t)tok * H;
#pragma unroll
            for (int nf = 0; nf < 4; nf++) {
                int h = h0 + wn + nf * 8 + 2 * (lane & 3);
                float v0 = acc[mf][nf][half * 2 + 0] + db[h];
                float v1 = acc[mf][nf][half * 2 + 1] + db[h + 1];
                atomicAdd(orow + h,     w * v0);
                atomicAdd(orow + h + 1, w * v1);
            }
        }
    }
}

// ---------------------------------------------------------------------------
extern "C" void kernel_launch(void* const* d_in, const int* in_sizes, int n_in,
                              void* d_out, int out_size) {
    const float* x     = (const float*)d_in[0];
    const float* rw    = (const float*)d_in[1];
    const float* rb    = (const float*)d_in[2];
    const float* gup   = (const float*)d_in[3];
    const float* gub   = (const float*)d_in[4];
    const float* dwn   = (const float*)d_in[5];
    const float* dbias = (const float*)d_in[6];
    float* out = (float*)d_out;

    cudaFuncSetAttribute(gateup_mma_kernel, cudaFuncAttributeMaxDynamicSharedMemorySize, SMEM_REQ);
    cudaFuncSetAttribute(down_mma_kernel,   cudaFuncAttributeMaxDynamicSharedMemorySize, SMEM_REQ);

    cudaMemsetAsync(out, 0, (size_t)out_size * sizeof(float));
    init_kernel<<<1, 32>>>();
    router_kernel<<<S, 256>>>(x, rw, rb);
    conv_x_kernel<<<(S * H / 4) / 256, 256>>>(x);

    {   // gate_up weights: [E][1024][4096] -> [E][4096][1024]  (device-bound outputs)
        dim3 g(H / 64, TWO_I / 32, E);
        transpose_split_kernel<0><<<g, 256>>>(gup);
    }
    {   // down weights: [E][2048][1024] -> [E][1024][2048]
        dim3 g(INTER / 64, H / 32, E);
        transpose_split_kernel<1><<<g, 256>>>(dwn);
    }
    {
        dim3 g(S / 128, INTER / 64, E);   // (16, 32, 8), early-exit past bucket count
        gateup_mma_kernel<<<g, 256, SMEM_REQ>>>(gub);
    }
    {
        dim3 g(S / 128, H / 128, E);      // (16, 8, 8)
        down_mma_kernel<<<g, 256, SMEM_REQ>>>(dbias, out);
    }
}

// round 7
// speedup vs baseline: 2.4737x; 1.0898x over previous
#include <cuda_runtime.h>
#include <cuda_bf16.h>
#include <cstdint>

#define S 2048
#define H 1024
#define E 8
#define INTER 2048
#define TWO_I 4096
#define ALPHA 1.702f
#define LIMIT 7.0f

// ---------------- device scratch (device-code references ONLY) ----------------
__device__ int   g_cnt[E];
__device__ int   g_tok[E * S];
__device__ float g_wt[E * S];
__device__ __align__(128) __nv_bfloat16 g_xhi[S * H];
__device__ __align__(128) __nv_bfloat16 g_xlo[S * H];
__device__ __align__(128) __nv_bfloat16 g_guh[(size_t)E * TWO_I * H];
__device__ __align__(128) __nv_bfloat16 g_gul[(size_t)E * TWO_I * H];
__device__ __align__(128) __nv_bfloat16 g_dwh[(size_t)E * H * INTER];
__device__ __align__(128) __nv_bfloat16 g_dwl[(size_t)E * H * INTER];
__device__ __align__(128) __nv_bfloat16 g_ah[(size_t)E * S * INTER];
__device__ __align__(128) __nv_bfloat16 g_al[(size_t)E * S * INTER];

// ---------------- helpers ----------------
__device__ __forceinline__ uint32_t s2u(const void* p) {
    uint32_t a;
    asm("{ .reg .u64 t; cvta.to.shared.u64 t, %1; cvt.u32.u64 %0, t; }" : "=r"(a) : "l"(p));
    return a;
}
__device__ __forceinline__ uint32_t swz128(uint32_t o) { return o ^ ((o >> 3) & 0x70); }

#define CP16(dst, src) \
    asm volatile("cp.async.cg.shared.global [%0], [%1], 16;" :: "r"(dst), "l"(src) : "memory")
#define CP_COMMIT() asm volatile("cp.async.commit_group;" ::: "memory")
#define CP_WAIT0()  asm volatile("cp.async.wait_group 0;" ::: "memory")

__device__ __forceinline__ void ldsm4(uint32_t addr, uint32_t* r) {
    asm volatile("ldmatrix.sync.aligned.m8n8.x4.shared.b16 {%0,%1,%2,%3}, [%4];"
                 : "=r"(r[0]), "=r"(r[1]), "=r"(r[2]), "=r"(r[3]) : "r"(addr));
}
__device__ __forceinline__ void mma16816(float* d, const uint32_t* a, uint32_t b0, uint32_t b1) {
    asm volatile(
        "mma.sync.aligned.m16n8k16.row.col.f32.bf16.bf16.f32 "
        "{%0,%1,%2,%3}, {%4,%5,%6,%7}, {%8,%9}, {%0,%1,%2,%3};"
        : "+f"(d[0]), "+f"(d[1]), "+f"(d[2]), "+f"(d[3])
        : "r"(a[0]), "r"(a[1]), "r"(a[2]), "r"(a[3]), "r"(b0), "r"(b1));
}

// Stage: Ah 16K | Al 16K | Bh 8K | Bl 8K = 48KB; 2 stages -> 2 CTAs/SM
#define AOFF_L 16384
#define BOFF_H 32768
#define BOFF_L 40960
#define STAGE  49152
#define SMEM_REQ (1024 + 2 * STAGE)

// one K=64 chunk of 3-term split MMA; block tile 128x64, warp tile 64x32 (4 warps)
__device__ __forceinline__ void compute_chunk(uint32_t base, int wm, int wn, int lane,
                                              float acc[4][4][4])
{
    uint32_t sA = base, sAl = base + AOFF_L, sB = base + BOFF_H, sBl = base + BOFF_L;
    int arow = wm + (lane & 15);
    int brow = wn + (lane & 15);
    uint32_t klane = (uint32_t)((lane >> 4) << 4);
#pragma unroll
    for (int ks = 0; ks < 4; ks++) {
        uint32_t ko = (uint32_t)(ks * 32) + klane;
        uint32_t ah[4][4], al[4][4];
#pragma unroll
        for (int mf = 0; mf < 4; mf++) {
            uint32_t off = swz128((uint32_t)((arow + mf * 16) * 128) + ko);
            ldsm4(sA + off, ah[mf]);
            ldsm4(sAl + off, al[mf]);
        }
#pragma unroll
        for (int nh = 0; nh < 2; nh++) {
            uint32_t boff = swz128((uint32_t)((brow + nh * 16) * 128) + ko);
            uint32_t bh[4], bl[4];
            ldsm4(sB + boff, bh);
            ldsm4(sBl + boff, bl);
#pragma unroll
            for (int mf = 0; mf < 4; mf++) {
                mma16816(acc[mf][2 * nh],     ah[mf], bh[0], bh[2]);
                mma16816(acc[mf][2 * nh],     al[mf], bh[0], bh[2]);
                mma16816(acc[mf][2 * nh],     ah[mf], bl[0], bl[2]);
                mma16816(acc[mf][2 * nh + 1], ah[mf], bh[1], bh[3]);
                mma16816(acc[mf][2 * nh + 1], al[mf], bh[1], bh[3]);
                mma16816(acc[mf][2 * nh + 1], ah[mf], bl[1], bl[3]);
            }
        }
    }
}

// 128 threads: A rows 0..127 (8 per thread), B rows 0..63 (4 per thread)
__device__ __forceinline__ void issue_chunk(
    uint32_t base, int k0,
    const __nv_bfloat16* Ah, const __nv_bfloat16* Al,
    const __nv_bfloat16* Bh, const __nv_bfloat16* Bl,
    const size_t* asrc, const size_t* bsrc,
    const uint32_t* adst, const uint32_t* bdst)
{
#pragma unroll
    for (int i = 0; i < 8; i++) {
        CP16(base +          adst[i], (const char*)(Ah + asrc[i] + k0));
        CP16(base + AOFF_L + adst[i], (const char*)(Al + asrc[i] + k0));
    }
#pragma unroll
    for (int i = 0; i < 4; i++) {
        CP16(base + BOFF_H + bdst[i], (const char*)(Bh + bsrc[i] + k0));
        CP16(base + BOFF_L + bdst[i], (const char*)(Bl + bsrc[i] + k0));
    }
    CP_COMMIT();
}

// ---------------------------------------------------------------------------
__global__ void init_kernel() {
    if (threadIdx.x < E) g_cnt[threadIdx.x] = 0;
}

// ---------------------------------------------------------------------------
__global__ __launch_bounds__(256) void router_kernel(
    const float* __restrict__ x, const float* __restrict__ rw, const float* __restrict__ rb)
{
    int t = blockIdx.x;
    int tid = threadIdx.x;
    const float* xr = x + (size_t)t * H;

    float acc[E];
#pragma unroll
    for (int e = 0; e < E; e++) acc[e] = 0.0f;
    for (int h = tid; h < H; h += 256) {
        float xv = xr[h];
        const float4* wrow = (const float4*)(rw + (size_t)h * E);
        float4 w0 = wrow[0], w1 = wrow[1];
        acc[0] += xv * w0.x; acc[1] += xv * w0.y; acc[2] += xv * w0.z; acc[3] += xv * w0.w;
        acc[4] += xv * w1.x; acc[5] += xv * w1.y; acc[6] += xv * w1.z; acc[7] += xv * w1.w;
    }
    __shared__ float sm[256 * E];
#pragma unroll
    for (int e = 0; e < E; e++) sm[tid * E + e] = acc[e];
    __syncthreads();
    for (int s = 128; s > 0; s >>= 1) {
        if (tid < s) {
#pragma unroll
            for (int e = 0; e < E; e++) sm[tid * E + e] += sm[(tid + s) * E + e];
        }
        __syncthreads();
    }
    if (tid == 0) {
        float v[E];
#pragma unroll
        for (int e = 0; e < E; e++) v[e] = sm[e] + rb[e];
        int i0 = 0;
#pragma unroll
        for (int e = 1; e < E; e++) if (v[e] > v[i0]) i0 = e;
        int i1 = -1;
#pragma unroll
        for (int e = 0; e < E; e++) {
            if (e == i0) continue;
            if (i1 < 0 || v[e] > v[i1]) i1 = e;
        }
        float e1 = expf(v[i1] - v[i0]);
        float den = 1.0f + e1;
        int p0 = atomicAdd(&g_cnt[i0], 1);
        g_tok[i0 * S + p0] = t; g_wt[i0 * S + p0] = 1.0f / den;
        int p1 = atomicAdd(&g_cnt[i1], 1);
        g_tok[i1 * S + p1] = t; g_wt[i1 * S + p1] = e1 / den;
    }
}

// ---------------------------------------------------------------------------
__global__ __launch_bounds__(256) void conv_x_kernel(const float* __restrict__ x) {
    int i = blockIdx.x * 256 + threadIdx.x;           // 4 elements each
    float4 v = ((const float4*)x)[i];
    __nv_bfloat16 h0 = __float2bfloat16(v.x), h1 = __float2bfloat16(v.y);
    __nv_bfloat16 h2 = __float2bfloat16(v.z), h3 = __float2bfloat16(v.w);
    __nv_bfloat16 l0 = __float2bfloat16(v.x - __bfloat162float(h0));
    __nv_bfloat16 l1 = __float2bfloat16(v.y - __bfloat162float(h1));
    __nv_bfloat16 l2 = __float2bfloat16(v.z - __bfloat162float(h2));
    __nv_bfloat16 l3 = __float2bfloat16(v.w - __bfloat162float(h3));
    ((__nv_bfloat162*)g_xhi)[2 * i]     = __halves2bfloat162(h0, h1);
    ((__nv_bfloat162*)g_xhi)[2 * i + 1] = __halves2bfloat162(h2, h3);
    ((__nv_bfloat162*)g_xlo)[2 * i]     = __halves2bfloat162(l0, l1);
    ((__nv_bfloat162*)g_xlo)[2 * i + 1] = __halves2bfloat162(l2, l3);
}

// ---------------------------------------------------------------------------
// weight transpose + split, outputs bound in DEVICE code.
// in [E][R][C] fp32 -> out [E][C][R] bf16 hi/lo. Tile 64(R) x 32(C).
// ---------------------------------------------------------------------------
template <int WHICH>   // 0 = gate_up (R=H, C=2I), 1 = down (R=INTER, C=H)
__global__ __launch_bounds__(256) void transpose_split_kernel(const float* __restrict__ in)
{
    const int R = (WHICH == 0) ? H : INTER;
    const int C = (WHICH == 0) ? TWO_I : H;
    __nv_bfloat16* ohi = (WHICH == 0) ? g_guh : g_dwh;
    __nv_bfloat16* olo = (WHICH == 0) ? g_gul : g_dwl;

    int e = blockIdx.z;
    int r0 = blockIdx.x * 64;
    int c0 = blockIdx.y * 32;
    __shared__ float t[64][33];
    int tx = threadIdx.x & 31, ty = threadIdx.x >> 5;
    const float* ib = in + ((size_t)e * R + r0) * C + c0;
#pragma unroll
    for (int i = 0; i < 8; i++)
        t[ty + 8 * i][tx] = ib[(size_t)(ty + 8 * i) * C + tx];
    __syncthreads();
#pragma unroll
    for (int i = 0; i < 4; i++) {
        int c = ty + 8 * i;
        float a = t[2 * tx][c], b = t[2 * tx + 1][c];
        __nv_bfloat16 ah = __float2bfloat16(a), bh = __float2bfloat16(b);
        __nv_bfloat16 al = __float2bfloat16(a - __bfloat162float(ah));
        __nv_bfloat16 bl = __float2bfloat16(b - __bfloat162float(bh));
        size_t o = ((size_t)e * C + c0 + c) * R + r0 + 2 * tx;
        *(__nv_bfloat162*)(ohi + o) = __halves2bfloat162(ah, bh);
        *(__nv_bfloat162*)(olo + o) = __halves2bfloat162(al, bl);
    }
}

// ---------------------------------------------------------------------------
// gate_up: CTA = (expert, 128-token M-tile, 32-j N-tile = 64 interleaved cols).
// 128 threads, 4 warps of 64x32. K = H = 1024, 16 chunks of 64.
// Single __syncthreads per chunk: wait0 -> sync -> issue(c+1) -> compute(c).
// ---------------------------------------------------------------------------
__global__ __launch_bounds__(128, 2) void gateup_mma_kernel(const float* __restrict__ gub) {
    int e = blockIdx.z, mt = blockIdx.x, nt = blockIdx.y;
    int cnt = g_cnt[e];
    if (mt * 128 >= cnt) return;

    extern __shared__ char smem[];
    uint32_t T0 = (s2u(smem) + 1023) & ~1023u;
    int tid = threadIdx.x, wid = tid >> 5, lane = tid & 31;
    int wm = (wid >> 1) * 64, wn = (wid & 1) * 32;
    int j0 = nt * 32;

    int seg = tid & 7;
    size_t asrc[8], bsrc[4];
    uint32_t adst[8], bdst[4];
#pragma unroll
    for (int i = 0; i < 8; i++) {
        int row = (tid >> 3) + 16 * i;                 // 0..127
        int tr = min(mt * 128 + row, cnt - 1);
        int tok = g_tok[e * S + tr];
        asrc[i] = (size_t)tok * H + seg * 8;
        adst[i] = swz128((uint32_t)(row * 128 + seg * 16));
    }
#pragma unroll
    for (int i = 0; i < 4; i++) {
        int row = (tid >> 3) + 16 * i;                 // 0..63
        int br = (row & 1) ? (INTER + j0 + (row >> 1)) : (j0 + (row >> 1));
        bsrc[i] = ((size_t)e * TWO_I + br) * H + seg * 8;
        bdst[i] = swz128((uint32_t)(row * 128 + seg * 16));
    }

    float acc[4][4][4];
#pragma unroll
    for (int a = 0; a < 4; a++)
#pragma unroll
        for (int b = 0; b < 4; b++)
#pragma unroll
            for (int c = 0; c < 4; c++) acc[a][b][c] = 0.0f;

    issue_chunk(T0, 0, g_xhi, g_xlo, g_guh, g_gul, asrc, bsrc, adst, bdst);
#pragma unroll 1
    for (int c = 0; c < 16; c++) {
        CP_WAIT0();
        __syncthreads();
        if (c + 1 < 16)
            issue_chunk(T0 + ((c + 1) & 1) * STAGE, (c + 1) * 64,
                        g_xhi, g_xlo, g_guh, g_gul, asrc, bsrc, adst, bdst);
        compute_chunk(T0 + (c & 1) * STAGE, wm, wn, lane, acc);
    }

    const float* gb = gub + (size_t)e * TWO_I;
#pragma unroll
    for (int mf = 0; mf < 4; mf++) {
        int r0 = wm + mf * 16 + (lane >> 2);
#pragma unroll
        for (int half = 0; half < 2; half++) {
            int mrow = mt * 128 + r0 + half * 8;
            if (mrow >= cnt) continue;
            size_t abase = ((size_t)e * S + mrow) * INTER;
#pragma unroll
            for (int nf = 0; nf < 4; nf++) {
                int nn = wn + nf * 8 + 2 * (lane & 3);
                int j = j0 + (nn >> 1);
                float g = acc[mf][nf][half * 2 + 0] + gb[j];
                float u = acc[mf][nf][half * 2 + 1] + gb[INTER + j];
                g = fminf(g, LIMIT);
                u = fminf(fmaxf(u, -LIMIT), LIMIT);
                float glu = g / (1.0f + __expf(-ALPHA * g));
                float av = (u + 1.0f) * glu;
                __nv_bfloat16 hi = __float2bfloat16(av);
                __nv_bfloat16 lo = __float2bfloat16(av - __bfloat162float(hi));
                g_ah[abase + j] = hi;
                g_al[abase + j] = lo;
            }
        }
    }
}

// ---------------------------------------------------------------------------
// down: CTA = (expert, 128-row M-tile, 64-h N-tile). 128 threads, 4 warps.
// K = INTER = 2048, 32 chunks of 64.
// ---------------------------------------------------------------------------
__global__ __launch_bounds__(128, 2) void down_mma_kernel(
    const float* __restrict__ dbias, float* __restrict__ out)
{
    int e = blockIdx.z, mt = blockIdx.x, nt = blockIdx.y;
    int cnt = g_cnt[e];
    if (mt * 128 >= cnt) return;

    extern __shared__ char smem[];
    uint32_t T0 = (s2u(smem) + 1023) & ~1023u;
    int tid = threadIdx.x, wid = tid >> 5, lane = tid & 31;
    int wm = (wid >> 1) * 64, wn = (wid & 1) * 32;
    int h0 = nt * 64;

    int seg = tid & 7;
    size_t asrc[8], bsrc[4];
    uint32_t adst[8], bdst[4];
#pragma unroll
    for (int i = 0; i < 8; i++) {
        int row = (tid >> 3) + 16 * i;
        int tr = min(mt * 128 + row, cnt - 1);
        asrc[i] = ((size_t)e * S + tr) * INTER + seg * 8;
        adst[i] = swz128((uint32_t)(row * 128 + seg * 16));
    }
#pragma unroll
    for (int i = 0; i < 4; i++) {
        int row = (tid >> 3) + 16 * i;                 // 0..63
        bsrc[i] = ((size_t)e * H + h0 + row) * INTER + seg * 8;
        bdst[i] = swz128((uint32_t)(row * 128 + seg * 16));
    }

    float acc[4][4][4];
#pragma unroll
    for (int a = 0; a < 4; a++)
#pragma unroll
        for (int b = 0; b < 4; b++)
#pragma unroll
            for (int c = 0; c < 4; c++) acc[a][b][c] = 0.0f;

    issue_chunk(T0, 0, g_ah, g_al, g_dwh, g_dwl, asrc, bsrc, adst, bdst);
#pragma unroll 1
    for (int c = 0; c < 32; c++) {
        CP_WAIT0();
        __syncthreads();
        if (c + 1 < 32)
            issue_chunk(T0 + ((c + 1) & 1) * STAGE, (c + 1) * 64,
                        g_ah, g_al, g_dwh, g_dwl, asrc, bsrc, adst, bdst);
        compute_chunk(T0 + (c & 1) * STAGE, wm, wn, lane, acc);
    }

    const float* db = dbias + (size_t)e * H;
#pragma unroll
    for (int mf = 0; mf < 4; mf++) {
        int r0 = wm + mf * 16 + (lane >> 2);
#pragma unroll
        for (int half = 0; half < 2; half++) {
            int mrow = mt * 128 + r0 + half * 8;
            if (mrow >= cnt) continue;
            int tok = g_tok[e * S + mrow];
            float w = g_wt[e * S + mrow];
            float* orow = out + (size_t)tok * H;
#pragma unroll
            for (int nf = 0; nf < 4; nf++) {
                int h = h0 + wn + nf * 8 + 2 * (lane & 3);
                float v0 = acc[mf][nf][half * 2 + 0] + db[h];
                float v1 = acc[mf][nf][half * 2 + 1] + db[h + 1];
                atomicAdd(orow + h,     w * v0);
                atomicAdd(orow + h + 1, w * v1);
            }
        }
    }
}

// ---------------------------------------------------------------------------
extern "C" void kernel_launch(void* const* d_in, const int* in_sizes, int n_in,
                              void* d_out, int out_size) {
    const float* x     = (const float*)d_in[0];
    const float* rw    = (const float*)d_in[1];
    const float* rb    = (const float*)d_in[2];
    const float* gup   = (const float*)d_in[3];
    const float* gub   = (const float*)d_in[4];
    const float* dwn   = (const float*)d_in[5];
    const float* dbias = (const float*)d_in[6];
    float* out = (float*)d_out;

    cudaFuncSetAttribute(gateup_mma_kernel, cudaFuncAttributeMaxDynamicSharedMemorySize, SMEM_REQ);
    cudaFuncSetAttribute(down_mma_kernel,   cudaFuncAttributeMaxDynamicSharedMemorySize, SMEM_REQ);

    cudaMemsetAsync(out, 0, (size_t)out_size * sizeof(float));
    init_kernel<<<1, 32>>>();
    router_kernel<<<S, 256>>>(x, rw, rb);
    conv_x_kernel<<<(S * H / 4) / 256, 256>>>(x);

    {   // gate_up weights: [E][1024][4096] -> [E][4096][1024]
        dim3 g(H / 64, TWO_I / 32, E);
        transpose_split_kernel<0><<<g, 256>>>(gup);
    }
    {   // down weights: [E][2048][1024] -> [E][1024][2048]
        dim3 g(INTER / 64, H / 32, E);
        transpose_split_kernel<1><<<g, 256>>>(dwn);
    }
    {
        dim3 g(S / 128, INTER / 32, E);   // (16, 64, 8), early-exit past bucket count
        gateup_mma_kernel<<<g, 128, SMEM_REQ>>>(gub);
    }
    {
        dim3 g(S / 128, H / 64, E);       // (16, 16, 8)
        down_mma_kernel<<<g, 128, SMEM_REQ>>>(dbias, out);
    }
}